// round 3
// baseline (speedup 1.0000x reference)
#include <cuda_runtime.h>
#include <cuda_bf16.h>
#include <mma.h>

using namespace nvcuda;

// Problem dims
#define B_   64
#define T_   1024
#define H_   512
#define M_   (B_ * T_)      // 65536 rows
#define L_   4
#define G3H  (3 * H_)       // 1536

// ---------------- static device scratch (no runtime allocation) ----------------
__device__ float g_hA[(size_t)M_ * H_];          // 134 MB
__device__ float g_hB[(size_t)M_ * H_];          // 134 MB
__device__ float g_gi[(size_t)M_ * G3H];         // 402 MB
__device__ float g_hbuf[2 * B_ * H_];            // double-buffered hidden state
__device__ int   g_bar[4];                       // per-group barrier counters

// ---------------- helpers ----------------
__device__ __forceinline__ void split_bf16(float v, __nv_bfloat16& hi, __nv_bfloat16& lo) {
    hi = __float2bfloat16(v);
    lo = __float2bfloat16(v - __bfloat162float(hi));
}

// =================================================================================
// GEMM: C[M,N] = act(A[M,K] @ W[N,K]^T + bias[N])
// bf16x2 split (3 MMA passes: hi*hi + hi*lo + lo*hi) -> ~fp32 accuracy.
// Block tile 128x128x32, 8 warps (2x4), warp tile 64x32 (4x2 of 16x16 frags).
// =================================================================================
#define BM 128
#define BN 128
#define BK 32
#define GLD 40   // padded smem leading dim (elements), multiple of 8

template<int RELU>
__global__ __launch_bounds__(256)
void gemm_kernel(const float* __restrict__ A, const float* __restrict__ W,
                 const float* __restrict__ bias, float* __restrict__ C,
                 int M, int N, int K)
{
    __shared__ __nv_bfloat16 sAh[BM * GLD];
    __shared__ __nv_bfloat16 sAl[BM * GLD];
    __shared__ __nv_bfloat16 sBh[BN * GLD];
    __shared__ __nv_bfloat16 sBl[BN * GLD];

    const int tid  = threadIdx.x;
    const int m0   = blockIdx.y * BM;
    const int n0   = blockIdx.x * BN;
    const int w    = tid >> 5;
    const int lane = tid & 31;
    const int wm   = w >> 2;   // 0..1
    const int wn   = w & 3;    // 0..3

    wmma::fragment<wmma::accumulator, 16, 16, 16, float> acc[4][2];
    #pragma unroll
    for (int i = 0; i < 4; i++)
        #pragma unroll
        for (int j = 0; j < 2; j++)
            wmma::fill_fragment(acc[i][j], 0.0f);

    const int r0 = tid >> 3;        // 0..31
    const int c4 = (tid & 7) * 4;   // 0,4,...,28

    for (int k0 = 0; k0 < K; k0 += BK) {
        #pragma unroll
        for (int rr = 0; rr < 4; rr++) {
            int r = r0 + rr * 32;
            float4 va = *(const float4*)&A[(size_t)(m0 + r) * K + k0 + c4];
            float4 vb = *(const float4*)&W[(size_t)(n0 + r) * K + k0 + c4];
            __nv_bfloat16 h, l;
            int base = r * GLD + c4;
            split_bf16(va.x, h, l); sAh[base + 0] = h; sAl[base + 0] = l;
            split_bf16(va.y, h, l); sAh[base + 1] = h; sAl[base + 1] = l;
            split_bf16(va.z, h, l); sAh[base + 2] = h; sAl[base + 2] = l;
            split_bf16(va.w, h, l); sAh[base + 3] = h; sAl[base + 3] = l;
            split_bf16(vb.x, h, l); sBh[base + 0] = h; sBl[base + 0] = l;
            split_bf16(vb.y, h, l); sBh[base + 1] = h; sBl[base + 1] = l;
            split_bf16(vb.z, h, l); sBh[base + 2] = h; sBl[base + 2] = l;
            split_bf16(vb.w, h, l); sBh[base + 3] = h; sBl[base + 3] = l;
        }
        __syncthreads();

        #pragma unroll
        for (int kk = 0; kk < BK; kk += 16) {
            wmma::fragment<wmma::matrix_b, 16, 16, 16, __nv_bfloat16, wmma::col_major> bh[2], bl[2];
            #pragma unroll
            for (int nf = 0; nf < 2; nf++) {
                wmma::load_matrix_sync(bh[nf], &sBh[(wn * 32 + nf * 16) * GLD + kk], GLD);
                wmma::load_matrix_sync(bl[nf], &sBl[(wn * 32 + nf * 16) * GLD + kk], GLD);
            }
            #pragma unroll
            for (int mf = 0; mf < 4; mf++) {
                wmma::fragment<wmma::matrix_a, 16, 16, 16, __nv_bfloat16, wmma::row_major> ah, al;
                wmma::load_matrix_sync(ah, &sAh[(wm * 64 + mf * 16) * GLD + kk], GLD);
                wmma::load_matrix_sync(al, &sAl[(wm * 64 + mf * 16) * GLD + kk], GLD);
                #pragma unroll
                for (int nf = 0; nf < 2; nf++) {
                    wmma::mma_sync(acc[mf][nf], ah, bh[nf], acc[mf][nf]);
                    wmma::mma_sync(acc[mf][nf], ah, bl[nf], acc[mf][nf]);
                    wmma::mma_sync(acc[mf][nf], al, bh[nf], acc[mf][nf]);
                }
            }
        }
        __syncthreads();
    }

    // Epilogue: smem roundtrip per warp (scratch reuses sAh: 2560 floats = 8 warps * 320)
    float* scr   = (float*)sAh;
    float* myscr = scr + w * 320;   // 16 x 20 floats
    #pragma unroll
    for (int mf = 0; mf < 4; mf++) {
        #pragma unroll
        for (int nf = 0; nf < 2; nf++) {
            wmma::store_matrix_sync(myscr, acc[mf][nf], 20, wmma::mem_row_major);
            __syncwarp();
            #pragma unroll
            for (int e = 0; e < 8; e++) {
                int idx = e * 32 + lane;
                int r = idx >> 4, c = idx & 15;
                int row = m0 + wm * 64 + mf * 16 + r;
                int col = n0 + wn * 32 + nf * 16 + c;
                float v = myscr[r * 20 + c] + __ldg(&bias[col]);
                if (RELU) v = fmaxf(v, 0.0f);
                C[(size_t)row * N + col] = v;
            }
            __syncwarp();
        }
    }
}

// =================================================================================
// Persistent GRU scan. 128 CTAs = 4 groups x 32 CTAs; group g owns batch rows
// [16g, 16g+16); CTA owns 16 hidden columns (48 gate columns). Per time step:
//   gh = h @ whh_sub^T  (bf16x2 split WMMA, K split across 2 warp-halves)
//   gates in fp32, h' written to double-buffered global hbuf, per-group
//   monotonic atomic barrier.
// =================================================================================
#define SW        520            // padded K leading dim (elems), multiple of 8
#define NBLK      32
#define GROUPS    4
#define BG        16
#define SCAN_SMEM (2*48*SW*2 + 2*16*SW*2 + 2*16*48*4 + 48*4)   // 139456 B

__global__ __launch_bounds__(192)
void scan_kernel(const float* __restrict__ gi, const float* __restrict__ whh,
                 const float* __restrict__ bhh, float* __restrict__ ys)
{
    extern __shared__ char smem_raw[];
    __nv_bfloat16* wh = (__nv_bfloat16*)smem_raw;   // 48 x SW
    __nv_bfloat16* wl = wh + 48 * SW;
    __nv_bfloat16* hh = wl + 48 * SW;               // 16 x SW
    __nv_bfloat16* hl = hh + 16 * SW;
    float* gh  = (float*)(hl + 16 * SW);            // [2][16][48]
    float* sbh = gh + 2 * 16 * 48;                  // 48

    const int tid   = threadIdx.x;
    const int g     = blockIdx.x >> 5;
    const int blk   = blockIdx.x & 31;
    const int c0    = blk * 16;
    const int w     = tid >> 5;
    const int ntile = w % 3;      // which gate chunk (r/z/n)
    const int khalf = w / 3;      // which K half
    const int bbase = g * BG;

    // Load this CTA's 48 rows of whh (rows {c0..}, {512+c0..}, {1024+c0..}), split hi/lo
    for (int i = tid; i < 48 * H_; i += 192) {
        int rl = i >> 9;            // 0..47
        int k  = i & 511;
        int grow = (rl >> 4) * H_ + c0 + (rl & 15);
        float v = whh[(size_t)grow * H_ + k];
        __nv_bfloat16 hi, lo; split_bf16(v, hi, lo);
        wh[rl * SW + k] = hi;
        wl[rl * SW + k] = lo;
    }
    for (int i = tid; i < 48; i += 192)
        sbh[i] = bhh[(i >> 4) * H_ + c0 + (i & 15)];
    __syncthreads();

    for (int t = 0; t < T_; t++) {
        const int cur = t & 1, nxt = cur ^ 1;
        const float* hsrc = g_hbuf + cur * (B_ * H_);

        // Stage h[16 x 512] from global (L2, bypass L1) into split bf16 smem
        for (int i = tid; i < BG * (H_ / 4); i += 192) {
            int b = i >> 7;
            int c = (i & 127) << 2;
            float4 v = __ldcg((const float4*)(hsrc + (size_t)(bbase + b) * H_ + c));
            __nv_bfloat16 hi, lo;
            int base = b * SW + c;
            split_bf16(v.x, hi, lo); hh[base + 0] = hi; hl[base + 0] = lo;
            split_bf16(v.y, hi, lo); hh[base + 1] = hi; hl[base + 1] = lo;
            split_bf16(v.z, hi, lo); hh[base + 2] = hi; hl[base + 2] = lo;
            split_bf16(v.w, hi, lo); hh[base + 3] = hi; hl[base + 3] = lo;
        }
        __syncthreads();

        // gh[16 x 48] via bf16x2 WMMA; warp = (ntile, khalf)
        {
            wmma::fragment<wmma::accumulator, 16, 16, 16, float> acc;
            wmma::fill_fragment(acc, 0.0f);
            const int kbase = khalf * 256;
            #pragma unroll
            for (int kk = 0; kk < 256; kk += 16) {
                int k = kbase + kk;
                wmma::fragment<wmma::matrix_a, 16, 16, 16, __nv_bfloat16, wmma::row_major> ah, al;
                wmma::fragment<wmma::matrix_b, 16, 16, 16, __nv_bfloat16, wmma::col_major> bh, bl;
                wmma::load_matrix_sync(ah, hh + k, SW);
                wmma::load_matrix_sync(al, hl + k, SW);
                wmma::load_matrix_sync(bh, wh + ntile * 16 * SW + k, SW);
                wmma::load_matrix_sync(bl, wl + ntile * 16 * SW + k, SW);
                wmma::mma_sync(acc, ah, bh, acc);
                wmma::mma_sync(acc, ah, bl, acc);
                wmma::mma_sync(acc, al, bh, acc);
            }
            wmma::store_matrix_sync(gh + khalf * 768 + ntile * 16, acc, 48, wmma::mem_row_major);
        }
        __syncthreads();

        // Gate epilogue: 256 (b,j) elements over 192 threads
        for (int idx = tid; idx < 256; idx += 192) {
            int b = idx >> 4, j = idx & 15;
            int c = c0 + j;
            size_t rowoff = (size_t)(bbase + b) * T_ + t;
            const float* gp = gi + rowoff * G3H;
            float gr = gh[b * 48 + j]      + gh[768 + b * 48 + j]      + sbh[j];
            float gz = gh[b * 48 + 16 + j] + gh[768 + b * 48 + 16 + j] + sbh[16 + j];
            float gn = gh[b * 48 + 32 + j] + gh[768 + b * 48 + 32 + j] + sbh[32 + j];
            float ir  = __ldg(gp + c);
            float iz  = __ldg(gp + H_ + c);
            float inn = __ldg(gp + 2 * H_ + c);
            float ho  = __ldcg(g_hbuf + cur * (B_ * H_) + (size_t)(bbase + b) * H_ + c);
            float r = 1.0f / (1.0f + expf(-(ir + gr)));
            float z = 1.0f / (1.0f + expf(-(iz + gz)));
            float n = tanhf(inn + r * gn);
            float hn = (1.0f - z) * n + z * ho;
            ys[rowoff * H_ + c] = hn;
            __stcg(g_hbuf + nxt * (B_ * H_) + (size_t)(bbase + b) * H_ + c, hn);
        }
        __threadfence();
        __syncthreads();
        if (tid == 0) {
            atomicAdd(&g_bar[g], 1);
            int target = NBLK * (t + 1);
            while (*(volatile int*)&g_bar[g] < target) __nanosleep(32);
        }
        __syncthreads();
    }
}

// =================================================================================
// Orchestration
// =================================================================================
extern "C" void kernel_launch(void* const* d_in, const int* in_sizes, int n_in,
                              void* d_out, int out_size)
{
    const float* x    = (const float*)d_in[0];
    const float* w_in = (const float*)d_in[1];
    const float* b_in = (const float*)d_in[2];
    const float* w_ih = (const float*)d_in[3];
    const float* w_hh = (const float*)d_in[4];
    const float* b_ih = (const float*)d_in[5];
    const float* b_hh = (const float*)d_in[6];
    const float* w_o1 = (const float*)d_in[7];
    const float* b_o1 = (const float*)d_in[8];
    const float* w_o2 = (const float*)d_in[9];
    const float* b_o2 = (const float*)d_in[10];
    float* out = (float*)d_out;
    (void)in_sizes; (void)n_in; (void)out_size;

    float *hA, *hB, *gi, *hbuf; int* bar;
    cudaGetSymbolAddress((void**)&hA,   g_hA);
    cudaGetSymbolAddress((void**)&hB,   g_hB);
    cudaGetSymbolAddress((void**)&gi,   g_gi);
    cudaGetSymbolAddress((void**)&hbuf, g_hbuf);
    cudaGetSymbolAddress((void**)&bar,  g_bar);

    cudaFuncSetAttribute(scan_kernel, cudaFuncAttributeMaxDynamicSharedMemorySize, SCAN_SMEM);

    dim3 blk(256);

    // input Linear + ReLU
    gemm_kernel<1><<<dim3(H_ / BN, M_ / BM), blk>>>(x, w_in, b_in, hA, M_, H_, H_);

    float* hcur = hA;
    float* hnxt = hB;
    for (int l = 0; l < L_; l++) {
        // gi = h @ w_ih^T + b_ih   (bias folded here; bhh added in scan)
        gemm_kernel<0><<<dim3(G3H / BN, M_ / BM), blk>>>(
            hcur, w_ih + (size_t)l * G3H * H_, b_ih + (size_t)l * G3H, gi, M_, G3H, H_);
        cudaMemsetAsync(hbuf, 0, sizeof(float) * 2 * B_ * H_);
        cudaMemsetAsync(bar,  0, sizeof(int) * GROUPS);
        scan_kernel<<<NBLK * GROUPS, 192, SCAN_SMEM>>>(
            gi, w_hh + (size_t)l * G3H * H_, b_hh + (size_t)l * G3H, hnxt);
        float* tmp = hcur; hcur = hnxt; hnxt = tmp;
    }

    // output MLP
    gemm_kernel<1><<<dim3(H_ / BN, M_ / BM), blk>>>(hcur, w_o1, b_o1, hnxt, M_, H_, H_);
    gemm_kernel<0><<<dim3(H_ / BN, M_ / BM), blk>>>(hnxt, w_o2, b_o2, out, M_, H_, H_);
}

// round 5
// speedup vs baseline: 1.3636x; 1.3636x over previous
#include <cuda_runtime.h>
#include <cuda_bf16.h>
#include <mma.h>

using namespace nvcuda;

// Problem dims
#define B_   64
#define T_   1024
#define H_   512
#define M_   (B_ * T_)      // 65536 rows
#define L_   4
#define G3H  (3 * H_)       // 1536

// ---------------- static device scratch (no runtime allocation) ----------------
__device__ float g_hA[(size_t)M_ * H_];          // 134 MB
__device__ float g_hB[(size_t)M_ * H_];          // 134 MB
__device__ float g_gi[(size_t)M_ * G3H];         // 402 MB
__device__ float g_hbuf[2 * B_ * H_];            // double-buffered hidden state
__device__ int   g_bar[4 * 32];                  // per-group barrier counters, padded 128B apart

// ---------------- helpers ----------------
__device__ __forceinline__ void split_bf16(float v, __nv_bfloat16& hi, __nv_bfloat16& lo) {
    hi = __float2bfloat16(v);
    lo = __float2bfloat16(v - __bfloat162float(hi));
}

__device__ __forceinline__ float fast_sigmoid(float x) {
    return __fdividef(1.0f, 1.0f + __expf(-x));
}
__device__ __forceinline__ float fast_tanh(float x) {
    float e = __expf(-2.0f * x);
    return __fdividef(1.0f - e, 1.0f + e);
}

// =================================================================================
// GEMM: C[M,N] = act(A[M,K] @ W[N,K]^T + bias[N])  (unchanged from R1 — known good)
// =================================================================================
#define BM 128
#define BN 128
#define BK 32
#define GLD 40   // padded smem leading dim (elements)

template<int RELU>
__global__ __launch_bounds__(256)
void gemm_kernel(const float* __restrict__ A, const float* __restrict__ W,
                 const float* __restrict__ bias, float* __restrict__ C,
                 int M, int N, int K)
{
    __shared__ __nv_bfloat16 sAh[BM * GLD];
    __shared__ __nv_bfloat16 sAl[BM * GLD];
    __shared__ __nv_bfloat16 sBh[BN * GLD];
    __shared__ __nv_bfloat16 sBl[BN * GLD];

    const int tid  = threadIdx.x;
    const int m0   = blockIdx.y * BM;
    const int n0   = blockIdx.x * BN;
    const int w    = tid >> 5;
    const int lane = tid & 31;
    const int wm   = w >> 2;
    const int wn   = w & 3;

    wmma::fragment<wmma::accumulator, 16, 16, 16, float> acc[4][2];
    #pragma unroll
    for (int i = 0; i < 4; i++)
        #pragma unroll
        for (int j = 0; j < 2; j++)
            wmma::fill_fragment(acc[i][j], 0.0f);

    const int r0 = tid >> 3;
    const int c4 = (tid & 7) * 4;

    for (int k0 = 0; k0 < K; k0 += BK) {
        #pragma unroll
        for (int rr = 0; rr < 4; rr++) {
            int r = r0 + rr * 32;
            float4 va = *(const float4*)&A[(size_t)(m0 + r) * K + k0 + c4];
            float4 vb = *(const float4*)&W[(size_t)(n0 + r) * K + k0 + c4];
            __nv_bfloat16 h, l;
            int base = r * GLD + c4;
            split_bf16(va.x, h, l); sAh[base + 0] = h; sAl[base + 0] = l;
            split_bf16(va.y, h, l); sAh[base + 1] = h; sAl[base + 1] = l;
            split_bf16(va.z, h, l); sAh[base + 2] = h; sAl[base + 2] = l;
            split_bf16(va.w, h, l); sAh[base + 3] = h; sAl[base + 3] = l;
            split_bf16(vb.x, h, l); sBh[base + 0] = h; sBl[base + 0] = l;
            split_bf16(vb.y, h, l); sBh[base + 1] = h; sBl[base + 1] = l;
            split_bf16(vb.z, h, l); sBh[base + 2] = h; sBl[base + 2] = l;
            split_bf16(vb.w, h, l); sBh[base + 3] = h; sBl[base + 3] = l;
        }
        __syncthreads();

        #pragma unroll
        for (int kk = 0; kk < BK; kk += 16) {
            wmma::fragment<wmma::matrix_b, 16, 16, 16, __nv_bfloat16, wmma::col_major> bh[2], bl[2];
            #pragma unroll
            for (int nf = 0; nf < 2; nf++) {
                wmma::load_matrix_sync(bh[nf], &sBh[(wn * 32 + nf * 16) * GLD + kk], GLD);
                wmma::load_matrix_sync(bl[nf], &sBl[(wn * 32 + nf * 16) * GLD + kk], GLD);
            }
            #pragma unroll
            for (int mf = 0; mf < 4; mf++) {
                wmma::fragment<wmma::matrix_a, 16, 16, 16, __nv_bfloat16, wmma::row_major> ah, al;
                wmma::load_matrix_sync(ah, &sAh[(wm * 64 + mf * 16) * GLD + kk], GLD);
                wmma::load_matrix_sync(al, &sAl[(wm * 64 + mf * 16) * GLD + kk], GLD);
                #pragma unroll
                for (int nf = 0; nf < 2; nf++) {
                    wmma::mma_sync(acc[mf][nf], ah, bh[nf], acc[mf][nf]);
                    wmma::mma_sync(acc[mf][nf], ah, bl[nf], acc[mf][nf]);
                    wmma::mma_sync(acc[mf][nf], al, bh[nf], acc[mf][nf]);
                }
            }
        }
        __syncthreads();
    }

    float* scr   = (float*)sAh;
    float* myscr = scr + w * 320;
    #pragma unroll
    for (int mf = 0; mf < 4; mf++) {
        #pragma unroll
        for (int nf = 0; nf < 2; nf++) {
            wmma::store_matrix_sync(myscr, acc[mf][nf], 20, wmma::mem_row_major);
            __syncwarp();
            #pragma unroll
            for (int e = 0; e < 8; e++) {
                int idx = e * 32 + lane;
                int r = idx >> 4, c = idx & 15;
                int row = m0 + wm * 64 + mf * 16 + r;
                int col = n0 + wn * 32 + nf * 16 + c;
                float v = myscr[r * 20 + c] + __ldg(&bias[col]);
                if (RELU) v = fmaxf(v, 0.0f);
                C[(size_t)row * N + col] = v;
            }
            __syncwarp();
        }
    }
}

// =================================================================================
// Persistent GRU scan (rewritten for latency):
//  - 128 CTAs = 4 batch-groups x 32 col-CTAs; CTA owns 16 hidden cols (48 gate cols)
//  - 384 threads = 12 warps = 3 gate tiles x 4 K-quarters (halved MMA chain)
//  - release-atomic + acquire-spin barrier (NO per-thread __threadfence)
//  - padded per-group counters (no L2 line sharing between groups)
//  - gi(t+1) register prefetch overlaps barrier + staging
//  - exact fp32 h staged to smem during h load (no extra L2 read in epilogue)
//  - __expf-based sigmoid/tanh
// =================================================================================
#define SW        520
#define NBLK      32
#define GROUPS    4
#define BG        16
#define NTHR      384
#define SCAN_SMEM (2*48*SW*2 + 2*16*SW*2 + 4*16*48*4 + 48*4 + 256*4)

__global__ __launch_bounds__(NTHR)
void scan_kernel(const float* __restrict__ gi, const float* __restrict__ whh,
                 const float* __restrict__ bhh, float* __restrict__ ys)
{
    extern __shared__ char smem_raw[];
    __nv_bfloat16* wh = (__nv_bfloat16*)smem_raw;   // 48 x SW
    __nv_bfloat16* wl = wh + 48 * SW;
    __nv_bfloat16* hh = wl + 48 * SW;               // 16 x SW
    __nv_bfloat16* hl = hh + 16 * SW;
    float* gh  = (float*)(hl + 16 * SW);            // [4][16][48] partials
    float* sbh = gh + 4 * 16 * 48;                  // 48
    float* hof = sbh + 48;                          // 256: exact fp32 h for owned cols

    const int tid   = threadIdx.x;
    const int g     = blockIdx.x >> 5;
    const int blk   = blockIdx.x & 31;
    const int c0    = blk * 16;
    const int w     = tid >> 5;
    const int ntile = w % 3;      // gate chunk (r/z/n)
    const int kq    = w / 3;      // K quarter 0..3
    const int bbase = g * BG;
    int* bar = &g_bar[g * 32];

    // Load this CTA's 48 rows of whh, split hi/lo
    for (int i = tid; i < 48 * H_; i += NTHR) {
        int rl = i >> 9;
        int k  = i & 511;
        int grow = (rl >> 4) * H_ + c0 + (rl & 15);
        float v = whh[(size_t)grow * H_ + k];
        __nv_bfloat16 hi, lo; split_bf16(v, hi, lo);
        wh[rl * SW + k] = hi;
        wl[rl * SW + k] = lo;
    }
    if (tid < 48)
        sbh[tid] = bhh[(tid >> 4) * H_ + c0 + (tid & 15)];
    __syncthreads();

    // gi prefetch: thread tid<256 owns (b = tid>>4, j = tid&15)
    float p_ir = 0.f, p_iz = 0.f, p_in = 0.f;
    const float* gbase = gi + (size_t)(bbase + (tid >> 4)) * T_ * G3H + (c0 + (tid & 15));
    if (tid < 256) {
        p_ir = __ldg(gbase);
        p_iz = __ldg(gbase + H_);
        p_in = __ldg(gbase + 2 * H_);
    }

    for (int t = 0; t < T_; t++) {
        const int cur = t & 1, nxt = cur ^ 1;
        const float* hsrc = g_hbuf + cur * (B_ * H_);

        // Stage h[16 x 512] (L2) -> split bf16 smem; keep exact fp32 for owned cols
        for (int i = tid; i < BG * (H_ / 4); i += NTHR) {
            int b = i >> 7;
            int c = (i & 127) << 2;
            float4 v = __ldcg((const float4*)(hsrc + (size_t)(bbase + b) * H_ + c));
            __nv_bfloat16 hi, lo;
            int base = b * SW + c;
            split_bf16(v.x, hi, lo); hh[base + 0] = hi; hl[base + 0] = lo;
            split_bf16(v.y, hi, lo); hh[base + 1] = hi; hl[base + 1] = lo;
            split_bf16(v.z, hi, lo); hh[base + 2] = hi; hl[base + 2] = lo;
            split_bf16(v.w, hi, lo); hh[base + 3] = hi; hl[base + 3] = lo;
            if ((unsigned)(c - c0) < 16u)
                *(float4*)&hof[b * 16 + (c - c0)] = v;
        }
        __syncthreads();

        // gh partial[kq][16 x 48] via bf16x2 WMMA; 12 warps = 3 gates x 4 K-quarters
        {
            wmma::fragment<wmma::accumulator, 16, 16, 16, float> acc;
            wmma::fill_fragment(acc, 0.0f);
            const int kbase = kq * 128;
            #pragma unroll
            for (int kk = 0; kk < 128; kk += 16) {
                int k = kbase + kk;
                wmma::fragment<wmma::matrix_a, 16, 16, 16, __nv_bfloat16, wmma::row_major> ah, al;
                wmma::fragment<wmma::matrix_b, 16, 16, 16, __nv_bfloat16, wmma::col_major> bh, bl;
                wmma::load_matrix_sync(ah, hh + k, SW);
                wmma::load_matrix_sync(al, hl + k, SW);
                wmma::load_matrix_sync(bh, wh + ntile * 16 * SW + k, SW);
                wmma::load_matrix_sync(bl, wl + ntile * 16 * SW + k, SW);
                wmma::mma_sync(acc, ah, bh, acc);
                wmma::mma_sync(acc, ah, bl, acc);
                wmma::mma_sync(acc, al, bh, acc);
            }
            wmma::store_matrix_sync(gh + kq * 768 + ntile * 16, acc, 48, wmma::mem_row_major);
        }
        __syncthreads();

        // Gate epilogue: 256 elements, one per thread (tid<256)
        if (tid < 256) {
            int b = tid >> 4, j = tid & 15;
            int c = c0 + j;
            size_t rowoff = (size_t)(bbase + b) * T_ + t;
            int o = b * 48 + j;
            float gr = gh[o]      + gh[768 + o]      + gh[1536 + o]      + gh[2304 + o]      + sbh[j];
            float gz = gh[o + 16] + gh[768 + o + 16] + gh[1536 + o + 16] + gh[2304 + o + 16] + sbh[16 + j];
            float gn = gh[o + 32] + gh[768 + o + 32] + gh[1536 + o + 32] + gh[2304 + o + 32] + sbh[32 + j];
            float ho = hof[b * 16 + j];
            float r = fast_sigmoid(p_ir + gr);
            float z = fast_sigmoid(p_iz + gz);
            float n = fast_tanh(p_in + r * gn);
            float hn = (1.0f - z) * n + z * ho;
            ys[rowoff * H_ + c] = hn;
            __stcg(g_hbuf + nxt * (B_ * H_) + (size_t)(bbase + b) * H_ + c, hn);
        }

        // Prefetch gi(t+1) — overlaps the barrier and next staging
        if (tid < 256 && t + 1 < T_) {
            const float* gp = gbase + (size_t)(t + 1) * G3H;
            p_ir = __ldg(gp);
            p_iz = __ldg(gp + H_);
            p_in = __ldg(gp + 2 * H_);
        }

        __syncthreads();   // all threads' stores ordered before thread0's release (cumulative)
        if (tid == 0) {
            asm volatile("red.release.gpu.global.add.s32 [%0], 1;" :: "l"(bar) : "memory");
            int target = NBLK * (t + 1);
            int v;
            do {
                asm volatile("ld.acquire.gpu.global.s32 %0, [%1];" : "=r"(v) : "l"(bar));
                if (v >= target) break;
                __nanosleep(20);
            } while (true);
        }
        __syncthreads();   // acquire propagates to all threads (cumulative)
    }
}

// =================================================================================
// Orchestration
// =================================================================================
extern "C" void kernel_launch(void* const* d_in, const int* in_sizes, int n_in,
                              void* d_out, int out_size)
{
    const float* x    = (const float*)d_in[0];
    const float* w_in = (const float*)d_in[1];
    const float* b_in = (const float*)d_in[2];
    const float* w_ih = (const float*)d_in[3];
    const float* w_hh = (const float*)d_in[4];
    const float* b_ih = (const float*)d_in[5];
    const float* b_hh = (const float*)d_in[6];
    const float* w_o1 = (const float*)d_in[7];
    const float* b_o1 = (const float*)d_in[8];
    const float* w_o2 = (const float*)d_in[9];
    const float* b_o2 = (const float*)d_in[10];
    float* out = (float*)d_out;
    (void)in_sizes; (void)n_in; (void)out_size;

    float *hA, *hB, *gi, *hbuf; int* bar;
    cudaGetSymbolAddress((void**)&hA,   g_hA);
    cudaGetSymbolAddress((void**)&hB,   g_hB);
    cudaGetSymbolAddress((void**)&gi,   g_gi);
    cudaGetSymbolAddress((void**)&hbuf, g_hbuf);
    cudaGetSymbolAddress((void**)&bar,  g_bar);

    cudaFuncSetAttribute(scan_kernel, cudaFuncAttributeMaxDynamicSharedMemorySize, SCAN_SMEM);

    dim3 blk(256);

    // input Linear + ReLU
    gemm_kernel<1><<<dim3(H_ / BN, M_ / BM), blk>>>(x, w_in, b_in, hA, M_, H_, H_);

    float* hcur = hA;
    float* hnxt = hB;
    for (int l = 0; l < L_; l++) {
        gemm_kernel<0><<<dim3(G3H / BN, M_ / BM), blk>>>(
            hcur, w_ih + (size_t)l * G3H * H_, b_ih + (size_t)l * G3H, gi, M_, G3H, H_);
        cudaMemsetAsync(hbuf, 0, sizeof(float) * 2 * B_ * H_);
        cudaMemsetAsync(bar,  0, sizeof(int) * 4 * 32);
        scan_kernel<<<NBLK * GROUPS, NTHR, SCAN_SMEM>>>(
            gi, w_hh + (size_t)l * G3H * H_, b_hh + (size_t)l * G3H, hnxt);
        float* tmp = hcur; hcur = hnxt; hnxt = tmp;
    }

    // output MLP
    gemm_kernel<1><<<dim3(H_ / BN, M_ / BM), blk>>>(hcur, w_o1, b_o1, hnxt, M_, H_, H_);
    gemm_kernel<0><<<dim3(H_ / BN, M_ / BM), blk>>>(hnxt, w_o2, b_o2, out, M_, H_, H_);
}

// round 6
// speedup vs baseline: 1.4453x; 1.0599x over previous
#include <cuda_runtime.h>
#include <cuda_bf16.h>
#include <mma.h>

using namespace nvcuda;

// Problem dims
#define B_   64
#define T_   1024
#define H_   512
#define M_   (B_ * T_)      // 65536 rows
#define L_   4
#define G3H  (3 * H_)       // 1536

// ---------------- static device scratch (no runtime allocation) ----------------
__device__ float g_hA[(size_t)M_ * H_];          // 134 MB
__device__ float g_hB[(size_t)M_ * H_];          // 134 MB
__device__ float g_gi[(size_t)M_ * G3H];         // 402 MB
__device__ float g_hbuf[2 * B_ * H_];            // double-buffered hidden state
__device__ int   g_bar[4 * 32];                  // per-group barrier counters, 128B apart

// ---------------- helpers ----------------
__device__ __forceinline__ void split_bf16(float v, __nv_bfloat16& hi, __nv_bfloat16& lo) {
    hi = __float2bfloat16(v);
    lo = __float2bfloat16(v - __bfloat162float(hi));
}

__device__ __forceinline__ float fast_sigmoid(float x) {
    return __fdividef(1.0f, 1.0f + __expf(-x));
}
__device__ __forceinline__ float fast_tanh(float x) {
    float e = __expf(-2.0f * x);
    return __fdividef(1.0f - e, 1.0f + e);
}

// =================================================================================
// GEMM: C[M,N] = act(A[M,K] @ W[N,K]^T + bias[N])  (unchanged — measured ~1.7us/launch)
// =================================================================================
#define BM 128
#define BN 128
#define BK 32
#define GLD 40

template<int RELU>
__global__ __launch_bounds__(256)
void gemm_kernel(const float* __restrict__ A, const float* __restrict__ W,
                 const float* __restrict__ bias, float* __restrict__ C,
                 int M, int N, int K)
{
    __shared__ __nv_bfloat16 sAh[BM * GLD];
    __shared__ __nv_bfloat16 sAl[BM * GLD];
    __shared__ __nv_bfloat16 sBh[BN * GLD];
    __shared__ __nv_bfloat16 sBl[BN * GLD];

    const int tid  = threadIdx.x;
    const int m0   = blockIdx.y * BM;
    const int n0   = blockIdx.x * BN;
    const int w    = tid >> 5;
    const int lane = tid & 31;
    const int wm   = w >> 2;
    const int wn   = w & 3;

    wmma::fragment<wmma::accumulator, 16, 16, 16, float> acc[4][2];
    #pragma unroll
    for (int i = 0; i < 4; i++)
        #pragma unroll
        for (int j = 0; j < 2; j++)
            wmma::fill_fragment(acc[i][j], 0.0f);

    const int r0 = tid >> 3;
    const int c4 = (tid & 7) * 4;

    for (int k0 = 0; k0 < K; k0 += BK) {
        #pragma unroll
        for (int rr = 0; rr < 4; rr++) {
            int r = r0 + rr * 32;
            float4 va = *(const float4*)&A[(size_t)(m0 + r) * K + k0 + c4];
            float4 vb = *(const float4*)&W[(size_t)(n0 + r) * K + k0 + c4];
            __nv_bfloat16 h, l;
            int base = r * GLD + c4;
            split_bf16(va.x, h, l); sAh[base + 0] = h; sAl[base + 0] = l;
            split_bf16(va.y, h, l); sAh[base + 1] = h; sAl[base + 1] = l;
            split_bf16(va.z, h, l); sAh[base + 2] = h; sAl[base + 2] = l;
            split_bf16(va.w, h, l); sAh[base + 3] = h; sAl[base + 3] = l;
            split_bf16(vb.x, h, l); sBh[base + 0] = h; sBl[base + 0] = l;
            split_bf16(vb.y, h, l); sBh[base + 1] = h; sBl[base + 1] = l;
            split_bf16(vb.z, h, l); sBh[base + 2] = h; sBl[base + 2] = l;
            split_bf16(vb.w, h, l); sBh[base + 3] = h; sBl[base + 3] = l;
        }
        __syncthreads();

        #pragma unroll
        for (int kk = 0; kk < BK; kk += 16) {
            wmma::fragment<wmma::matrix_b, 16, 16, 16, __nv_bfloat16, wmma::col_major> bh[2], bl[2];
            #pragma unroll
            for (int nf = 0; nf < 2; nf++) {
                wmma::load_matrix_sync(bh[nf], &sBh[(wn * 32 + nf * 16) * GLD + kk], GLD);
                wmma::load_matrix_sync(bl[nf], &sBl[(wn * 32 + nf * 16) * GLD + kk], GLD);
            }
            #pragma unroll
            for (int mf = 0; mf < 4; mf++) {
                wmma::fragment<wmma::matrix_a, 16, 16, 16, __nv_bfloat16, wmma::row_major> ah, al;
                wmma::load_matrix_sync(ah, &sAh[(wm * 64 + mf * 16) * GLD + kk], GLD);
                wmma::load_matrix_sync(al, &sAl[(wm * 64 + mf * 16) * GLD + kk], GLD);
                #pragma unroll
                for (int nf = 0; nf < 2; nf++) {
                    wmma::mma_sync(acc[mf][nf], ah, bh[nf], acc[mf][nf]);
                    wmma::mma_sync(acc[mf][nf], ah, bl[nf], acc[mf][nf]);
                    wmma::mma_sync(acc[mf][nf], al, bh[nf], acc[mf][nf]);
                }
            }
        }
        __syncthreads();
    }

    float* scr   = (float*)sAh;
    float* myscr = scr + w * 320;
    #pragma unroll
    for (int mf = 0; mf < 4; mf++) {
        #pragma unroll
        for (int nf = 0; nf < 2; nf++) {
            wmma::store_matrix_sync(myscr, acc[mf][nf], 20, wmma::mem_row_major);
            __syncwarp();
            #pragma unroll
            for (int e = 0; e < 8; e++) {
                int idx = e * 32 + lane;
                int r = idx >> 4, c = idx & 15;
                int row = m0 + wm * 64 + mf * 16 + r;
                int col = n0 + wn * 32 + nf * 16 + c;
                float v = myscr[r * 20 + c] + __ldg(&bias[col]);
                if (RELU) v = fmaxf(v, 0.0f);
                C[(size_t)row * N + col] = v;
            }
            __syncwarp();
        }
    }
}

// =================================================================================
// Persistent GRU scan, R6:
//  - weights held in PERSISTENT REGISTER FRAGMENTS (loaded once; no weight smem,
//    no weight LDSM in the per-step inner loop)
//  - tight ld.acquire spin barrier (NO __nanosleep)
//  - 128 CTAs = 4 batch-groups x 32 col-CTAs; 384 thr = 3 gate tiles x 4 K-quarters
//  - gi(t+1) register prefetch; exact fp32 h kept in smem for the z*h term
// =================================================================================
#define SW        520
#define NBLK      32
#define GROUPS    4
#define BG        16
#define NTHR      384
// smem: init needs 48*SW bf16 (49,920B); steady needs 2*16*SW*2 + 4*768*4 + 48*4 + 256*4 = 46,784B
#define SCAN_SMEM 50048

typedef wmma::fragment<wmma::matrix_b, 16, 16, 16, __nv_bfloat16, wmma::col_major> bfrag_t;
typedef wmma::fragment<wmma::matrix_a, 16, 16, 16, __nv_bfloat16, wmma::row_major> afrag_t;

__global__ __launch_bounds__(NTHR)
void scan_kernel(const float* __restrict__ gi, const float* __restrict__ whh,
                 const float* __restrict__ bhh, float* __restrict__ ys)
{
    extern __shared__ char smem_raw[];
    // init-time alias (weight staging), dead after fragment load:
    __nv_bfloat16* wtmp = (__nv_bfloat16*)smem_raw;        // 48 x SW
    // steady-state layout (overlaps wtmp):
    __nv_bfloat16* hh = (__nv_bfloat16*)smem_raw;          // 16 x SW
    __nv_bfloat16* hl = hh + 16 * SW;                      // 16 x SW
    float* gh  = (float*)(hl + 16 * SW);                   // [4][16][48] partials
    float* sbh = gh + 4 * 768;                             // 48
    float* hof = sbh + 48;                                 // 256 exact fp32 h

    const int tid   = threadIdx.x;
    const int g     = blockIdx.x >> 5;
    const int blk   = blockIdx.x & 31;
    const int c0    = blk * 16;
    const int w     = tid >> 5;
    const int ntile = w % 3;      // gate chunk (r/z/n)
    const int kq    = w / 3;      // K quarter 0..3
    const int bbase = g * BG;
    int* bar = &g_bar[g * 32];

    // ---- init: load weight fragments into registers (hi pass, then lo pass) ----
    bfrag_t bhf[8], blf[8];
    for (int i = tid; i < 48 * H_; i += NTHR) {
        int rl = i >> 9, k = i & 511;
        int grow = (rl >> 4) * H_ + c0 + (rl & 15);
        wtmp[rl * SW + k] = __float2bfloat16(whh[(size_t)grow * H_ + k]);
    }
    __syncthreads();
    #pragma unroll
    for (int i = 0; i < 8; i++)
        wmma::load_matrix_sync(bhf[i], wtmp + ntile * 16 * SW + kq * 128 + i * 16, SW);
    __syncthreads();
    for (int i = tid; i < 48 * H_; i += NTHR) {
        int rl = i >> 9, k = i & 511;
        int grow = (rl >> 4) * H_ + c0 + (rl & 15);
        float v = whh[(size_t)grow * H_ + k];
        wtmp[rl * SW + k] = __float2bfloat16(v - __bfloat162float(__float2bfloat16(v)));
    }
    __syncthreads();
    #pragma unroll
    for (int i = 0; i < 8; i++)
        wmma::load_matrix_sync(blf[i], wtmp + ntile * 16 * SW + kq * 128 + i * 16, SW);
    __syncthreads();
    if (tid < 48)
        sbh[tid] = bhh[(tid >> 4) * H_ + c0 + (tid & 15)];
    __syncthreads();

    // gi prefetch: thread tid<256 owns (b = tid>>4, j = tid&15)
    float p_ir = 0.f, p_iz = 0.f, p_in = 0.f;
    const float* gbase = gi + (size_t)(bbase + (tid >> 4)) * T_ * G3H + (c0 + (tid & 15));
    if (tid < 256) {
        p_ir = __ldg(gbase);
        p_iz = __ldg(gbase + H_);
        p_in = __ldg(gbase + 2 * H_);
    }

    for (int t = 0; t < T_; t++) {
        const int cur = t & 1, nxt = cur ^ 1;
        const float* hsrc = g_hbuf + cur * (B_ * H_);

        // Stage h[16 x 512] (L2) -> split bf16 smem; keep exact fp32 for owned cols
        for (int i = tid; i < BG * (H_ / 4); i += NTHR) {
            int b = i >> 7;
            int c = (i & 127) << 2;
            float4 v = __ldcg((const float4*)(hsrc + (size_t)(bbase + b) * H_ + c));
            __nv_bfloat16 hi, lo;
            int base = b * SW + c;
            split_bf16(v.x, hi, lo); hh[base + 0] = hi; hl[base + 0] = lo;
            split_bf16(v.y, hi, lo); hh[base + 1] = hi; hl[base + 1] = lo;
            split_bf16(v.z, hi, lo); hh[base + 2] = hi; hl[base + 2] = lo;
            split_bf16(v.w, hi, lo); hh[base + 3] = hi; hl[base + 3] = lo;
            if ((unsigned)(c - c0) < 16u)
                *(float4*)&hof[b * 16 + (c - c0)] = v;
        }
        __syncthreads();

        // gh partial[kq][16 x 48]: per k-iter only 2 LDSM (A hi/lo) + 3 MMA with
        // register-resident weight fragments
        {
            wmma::fragment<wmma::accumulator, 16, 16, 16, float> acc;
            wmma::fill_fragment(acc, 0.0f);
            const int kbase = kq * 128;
            afrag_t ah, al;
            #pragma unroll
            for (int i = 0; i < 8; i++) {
                int k = kbase + i * 16;
                wmma::load_matrix_sync(ah, hh + k, SW);
                wmma::load_matrix_sync(al, hl + k, SW);
                wmma::mma_sync(acc, ah, bhf[i], acc);
                wmma::mma_sync(acc, ah, blf[i], acc);
                wmma::mma_sync(acc, al, bhf[i], acc);
            }
            wmma::store_matrix_sync(gh + kq * 768 + ntile * 16, acc, 48, wmma::mem_row_major);
        }
        __syncthreads();

        // Gate epilogue: 256 elements, one per thread (tid<256)
        if (tid < 256) {
            int b = tid >> 4, j = tid & 15;
            int c = c0 + j;
            size_t rowoff = (size_t)(bbase + b) * T_ + t;
            int o = b * 48 + j;
            float gr = gh[o]      + gh[768 + o]      + gh[1536 + o]      + gh[2304 + o]      + sbh[j];
            float gz = gh[o + 16] + gh[768 + o + 16] + gh[1536 + o + 16] + gh[2304 + o + 16] + sbh[16 + j];
            float gn = gh[o + 32] + gh[768 + o + 32] + gh[1536 + o + 32] + gh[2304 + o + 32] + sbh[32 + j];
            float ho = hof[b * 16 + j];
            float r = fast_sigmoid(p_ir + gr);
            float z = fast_sigmoid(p_iz + gz);
            float n = fast_tanh(p_in + r * gn);
            float hn = (1.0f - z) * n + z * ho;
            ys[rowoff * H_ + c] = hn;
            __stcg(g_hbuf + nxt * (B_ * H_) + (size_t)(bbase + b) * H_ + c, hn);
        }

        // Prefetch gi(t+1) — overlaps the barrier
        if (tid < 256 && t + 1 < T_) {
            const float* gp = gbase + (size_t)(t + 1) * G3H;
            p_ir = __ldg(gp);
            p_iz = __ldg(gp + H_);
            p_in = __ldg(gp + 2 * H_);
        }

        __syncthreads();   // order all h' stores before thread0's release
        if (tid == 0) {
            asm volatile("red.release.gpu.global.add.s32 [%0], 1;" :: "l"(bar) : "memory");
            const int target = NBLK * (t + 1);
            int v;
            do {
                asm volatile("ld.acquire.gpu.global.s32 %0, [%1];" : "=r"(v) : "l"(bar));
            } while (v < target);       // tight spin — no nanosleep
        }
        __syncthreads();   // acquire propagates to all threads
    }
}

// =================================================================================
// Orchestration
// =================================================================================
extern "C" void kernel_launch(void* const* d_in, const int* in_sizes, int n_in,
                              void* d_out, int out_size)
{
    const float* x    = (const float*)d_in[0];
    const float* w_in = (const float*)d_in[1];
    const float* b_in = (const float*)d_in[2];
    const float* w_ih = (const float*)d_in[3];
    const float* w_hh = (const float*)d_in[4];
    const float* b_ih = (const float*)d_in[5];
    const float* b_hh = (const float*)d_in[6];
    const float* w_o1 = (const float*)d_in[7];
    const float* b_o1 = (const float*)d_in[8];
    const float* w_o2 = (const float*)d_in[9];
    const float* b_o2 = (const float*)d_in[10];
    float* out = (float*)d_out;
    (void)in_sizes; (void)n_in; (void)out_size;

    float *hA, *hB, *gi, *hbuf; int* bar;
    cudaGetSymbolAddress((void**)&hA,   g_hA);
    cudaGetSymbolAddress((void**)&hB,   g_hB);
    cudaGetSymbolAddress((void**)&gi,   g_gi);
    cudaGetSymbolAddress((void**)&hbuf, g_hbuf);
    cudaGetSymbolAddress((void**)&bar,  g_bar);

    cudaFuncSetAttribute(scan_kernel, cudaFuncAttributeMaxDynamicSharedMemorySize, SCAN_SMEM);

    dim3 blk(256);

    // input Linear + ReLU
    gemm_kernel<1><<<dim3(H_ / BN, M_ / BM), blk>>>(x, w_in, b_in, hA, M_, H_, H_);

    float* hcur = hA;
    float* hnxt = hB;
    for (int l = 0; l < L_; l++) {
        gemm_kernel<0><<<dim3(G3H / BN, M_ / BM), blk>>>(
            hcur, w_ih + (size_t)l * G3H * H_, b_ih + (size_t)l * G3H, gi, M_, G3H, H_);
        cudaMemsetAsync(hbuf, 0, sizeof(float) * 2 * B_ * H_);
        cudaMemsetAsync(bar,  0, sizeof(int) * 4 * 32);
        scan_kernel<<<NBLK * GROUPS, NTHR, SCAN_SMEM>>>(
            gi, w_hh + (size_t)l * G3H * H_, b_hh + (size_t)l * G3H, hnxt);
        float* tmp = hcur; hcur = hnxt; hnxt = tmp;
    }

    // output MLP
    gemm_kernel<1><<<dim3(H_ / BN, M_ / BM), blk>>>(hcur, w_o1, b_o1, hnxt, M_, H_, H_);
    gemm_kernel<0><<<dim3(H_ / BN, M_ / BM), blk>>>(hnxt, w_o2, b_o2, out, M_, H_, H_);
}